// round 12
// baseline (speedup 1.0000x reference)
#include <cuda_runtime.h>
#include <cstdint>

// R12 = R11 (best: 84.4us) + (a) 4x16KB TMA split per row slot for finer
// DRAM/LTS interleaving, (b) butterfly warpsums reduce (1 LDS + 5 SHFL
// instead of 32 broadcast LDS per thread).

#define THREADS 1024
#define MAXCHUNK 4   // N/4/THREADS = 16384/4/1024
#define STAGES 3
#define TMA_SPLIT 4

__device__ unsigned g_ticket;   // zero-initialized at module load
__device__ unsigned g_done;

__global__ __launch_bounds__(THREADS, 1)
void sensory_persistent12(const float* __restrict__ enc,
                          const float* __restrict__ w,
                          const int*   __restrict__ pref,
                          float* __restrict__ out,
                          int B, int N, int F, int fmask)
{
    extern __shared__ __align__(128) unsigned char smem_dyn[];
    __shared__ __align__(8) unsigned long long mbar[STAGES];
    __shared__ float warpsums[THREADS / 32];
    __shared__ int rowids_sm[STAGES];

    const int tid = threadIdx.x;
    const unsigned rowbytes = (unsigned)F * 4u;
    const unsigned qbytes = rowbytes / TMA_SPLIT;

    const uint32_t buf_base = (uint32_t)__cvta_generic_to_shared(smem_dyn);
    const uint32_t bar_base = (uint32_t)__cvta_generic_to_shared(&mbar[0]);

    if (tid == 0) {
        #pragma unroll
        for (int s = 0; s < STAGES; ++s)
            asm volatile("mbarrier.init.shared::cta.b64 [%0], 1;"
                         :: "r"(bar_base + 8u * s) : "memory");
        asm volatile("fence.proxy.async.shared::cta;" ::: "memory");
    }
    __syncthreads();

    // ---- preload prefs as packed 2x16-bit byte offsets + weights ----
    const int n4 = N >> 2;
    uint32_t plo[MAXCHUNK], phi[MAXCHUNK];   // (x | y<<16), (z | w<<16)
    float4 wv[MAXCHUNK];
    {
        const int4*   pref4 = (const int4*)pref;
        const float4* w4    = (const float4*)w;
        #pragma unroll
        for (int k = 0; k < MAXCHUNK; ++k) {
            int i4 = tid + k * THREADS;
            if (i4 < n4) {
                int4 p = pref4[i4];
                uint32_t ox, oy, oz, ow;
                if (fmask) {
                    ox = (uint32_t)(p.x & fmask) << 2;
                    oy = (uint32_t)(p.y & fmask) << 2;
                    oz = (uint32_t)(p.z & fmask) << 2;
                    ow = (uint32_t)(p.w & fmask) << 2;
                } else {
                    ox = ((unsigned)p.x % (unsigned)F) << 2;
                    oy = ((unsigned)p.y % (unsigned)F) << 2;
                    oz = ((unsigned)p.z % (unsigned)F) << 2;
                    ow = ((unsigned)p.w % (unsigned)F) << 2;
                }
                plo[k] = ox | (oy << 16);
                phi[k] = oz | (ow << 16);
                wv[k]  = w4[i4];
            } else {
                plo[k] = phi[k] = 0;
                wv[k] = make_float4(0.f, 0.f, 0.f, 0.f);
            }
        }
    }

    // ---- prologue: claim and issue first two rows (TMA_SPLIT copies each) ----
    if (tid == 0) {
        #pragma unroll
        for (int s = 0; s < 2; ++s) {
            int r = (int)atomicAdd(&g_ticket, 1u);
            rowids_sm[s] = r;
            if (r < B) {
                const uint32_t mb = bar_base + 8u * s;
                const uint32_t bf = buf_base + s * rowbytes;
                const char* src = (const char*)(enc + (size_t)r * (size_t)F);
                asm volatile("mbarrier.arrive.expect_tx.shared::cta.b64 _, [%0], %1;"
                             :: "r"(mb), "r"(rowbytes) : "memory");
                #pragma unroll
                for (int q = 0; q < TMA_SPLIT; ++q) {
                    asm volatile("cp.async.bulk.shared::cta.global.mbarrier::complete_tx::bytes "
                                 "[%0], [%1], %2, [%3];"
                                 :: "r"(bf + q * qbytes), "l"(src + q * qbytes),
                                    "r"(qbytes), "r"(mb) : "memory");
                }
            }
        }
    }
    __syncthreads();

    int cur = 0, nxt2 = 2;   // nxt2 = (cur + 2) % STAGES
    int par = 0;

    for (;;) {
        const int r = rowids_sm[cur];   // claimed 2 iterations ago (or prologue)
        if (r >= B) break;

        // ---- claim + issue refill TMA at TOP of iteration (buffer nxt2 free
        // since before the PREVIOUS iteration's __syncthreads) ----
        if (tid == 0) {
            int r2 = (int)atomicAdd(&g_ticket, 1u);
            rowids_sm[nxt2] = r2;
            if (r2 < B) {
                const uint32_t mb = bar_base + 8u * nxt2;
                const uint32_t bf = buf_base + nxt2 * rowbytes;
                const char* src = (const char*)(enc + (size_t)r2 * (size_t)F);
                asm volatile("mbarrier.arrive.expect_tx.shared::cta.b64 _, [%0], %1;"
                             :: "r"(mb), "r"(rowbytes) : "memory");
                #pragma unroll
                for (int q = 0; q < TMA_SPLIT; ++q) {
                    asm volatile("cp.async.bulk.shared::cta.global.mbarrier::complete_tx::bytes "
                                 "[%0], [%1], %2, [%3];"
                                 :: "r"(bf + q * qbytes), "l"(src + q * qbytes),
                                    "r"(qbytes), "r"(mb) : "memory");
                }
            }
        }

        // ---- wait for current buffer ----
        {
            const uint32_t mb = bar_base + 8u * cur;
            uint32_t done;
            asm volatile("{ .reg .pred p; "
                         "mbarrier.try_wait.parity.acquire.cta.shared::cta.b64 p, [%1], %2; "
                         "selp.b32 %0, 1, 0, p; }"
                         : "=r"(done) : "r"(mb), "r"((uint32_t)par) : "memory");
            if (!done) {
                asm volatile("{ .reg .pred P1; "
                             "WL%=: mbarrier.try_wait.parity.acquire.cta.shared::cta.b64 P1, [%0], %1, 0x989680; "
                             "@P1 bra.uni WD%=; bra.uni WL%=; WD%=: }"
                             :: "r"(mb), "r"((uint32_t)par) : "memory");
            }
        }

        const char* srow = (const char*)smem_dyn + (size_t)cur * rowbytes;

        // ---- gather into registers + local sum ----
        float lsum = 0.0f;
        float4 vals[MAXCHUNK];
        #pragma unroll
        for (int k = 0; k < MAXCHUNK; ++k) {
            float4 v;
            v.x = *(const float*)(srow + (plo[k] & 0xFFFFu)) * wv[k].x;
            v.y = *(const float*)(srow + (plo[k] >> 16))     * wv[k].y;
            v.z = *(const float*)(srow + (phi[k] & 0xFFFFu)) * wv[k].z;
            v.w = *(const float*)(srow + (phi[k] >> 16))     * wv[k].w;
            vals[k] = v;
            lsum += (v.x + v.y) + (v.z + v.w);
        }

        // ---- warp partial sums ----
        #pragma unroll
        for (int off = 16; off > 0; off >>= 1)
            lsum += __shfl_down_sync(0xFFFFFFFFu, lsum, off);
        if ((tid & 31) == 0) warpsums[tid >> 5] = lsum;
        __syncthreads();   // sums visible AND all reads of srow done -> release point

        // ---- butterfly final reduce: 1 LDS + 5 SHFL, all lanes get total ----
        float tot = warpsums[tid & 31];   // THREADS/32 == 32 entries
        #pragma unroll
        for (int off = 16; off > 0; off >>= 1)
            tot += __shfl_xor_sync(0xFFFFFFFFu, tot, off);
        const float sub = (0.1f / (float)N) * tot;

        // ---- epilogue: subtract + relu, streaming float4 stores ----
        float4* out4 = (float4*)(out + (size_t)r * (size_t)N);
        #pragma unroll
        for (int k = 0; k < MAXCHUNK; ++k) {
            int i4 = tid + k * THREADS;
            float4 v = vals[k];
            float4 o;
            o.x = fmaxf(v.x - sub, 0.0f);
            o.y = fmaxf(v.y - sub, 0.0f);
            o.z = fmaxf(v.z - sub, 0.0f);
            o.w = fmaxf(v.w - sub, 0.0f);
            __stcs(out4 + i4, o);
        }

        // advance ring
        cur  = (cur == STAGES - 1) ? 0 : cur + 1;
        nxt2 = (nxt2 == STAGES - 1) ? 0 : nxt2 + 1;
        if (cur == 0) par ^= 1;
    }

    // ---- self-reset for the next (graph-replayed) launch ----
    if (tid == 0) {
        __threadfence();
        unsigned d = atomicAdd(&g_done, 1u);
        if (d == gridDim.x - 1u) {
            g_ticket = 0u;
            g_done   = 0u;
            __threadfence();
        }
    }
}

extern "C" void kernel_launch(void* const* d_in, const int* in_sizes, int n_in,
                              void* d_out, int out_size)
{
    const float* enc  = (const float*)d_in[0];
    const float* w    = (const float*)d_in[1];
    const int*   pref = (const int*)d_in[2];
    float*       out  = (float*)d_out;

    const int N = in_sizes[1];
    const int B = out_size / N;
    const int F = (int)((long long)in_sizes[0] / (long long)B);
    const int fmask = ((F & (F - 1)) == 0) ? (F - 1) : 0;

    int dev = 0;
    cudaGetDevice(&dev);
    int sms = 148;
    cudaDeviceGetAttribute(&sms, cudaDevAttrMultiProcessorCount, dev);
    int grid = (B < sms) ? B : sms;

    const int smem = STAGES * F * (int)sizeof(float);
    cudaFuncSetAttribute(sensory_persistent12,
                         cudaFuncAttributeMaxDynamicSharedMemorySize, smem);

    sensory_persistent12<<<grid, THREADS, smem>>>(enc, w, pref, out, B, N, F, fmask);
}

// round 14
// speedup vs baseline: 1.0030x; 1.0030x over previous
#include <cuda_runtime.h>
#include <cstdint>

// R13 = R12 hot loop (best in-kernel: 80.7us) with the prologue TMA issue
// hoisted BEFORE the pref/weight register preload, so the first row's DRAM
// fetch overlaps the ~128KB/CTA preload burst at every replay start.

#define THREADS 1024
#define MAXCHUNK 4   // N/4/THREADS = 16384/4/1024
#define STAGES 3
#define TMA_SPLIT 4

__device__ unsigned g_ticket;   // zero-initialized at module load
__device__ unsigned g_done;

__global__ __launch_bounds__(THREADS, 1)
void sensory_persistent13(const float* __restrict__ enc,
                          const float* __restrict__ w,
                          const int*   __restrict__ pref,
                          float* __restrict__ out,
                          int B, int N, int F, int fmask)
{
    extern __shared__ __align__(128) unsigned char smem_dyn[];
    __shared__ __align__(8) unsigned long long mbar[STAGES];
    __shared__ float warpsums[THREADS / 32];
    __shared__ int rowids_sm[STAGES];

    const int tid = threadIdx.x;
    const unsigned rowbytes = (unsigned)F * 4u;
    const unsigned qbytes = rowbytes / TMA_SPLIT;

    const uint32_t buf_base = (uint32_t)__cvta_generic_to_shared(smem_dyn);
    const uint32_t bar_base = (uint32_t)__cvta_generic_to_shared(&mbar[0]);

    // ---- tid 0: init mbarriers AND immediately claim+issue first two rows.
    // Other threads don't touch the barriers until after the __syncthreads
    // below, so no pre-init visibility is required for them here.
    if (tid == 0) {
        #pragma unroll
        for (int s = 0; s < STAGES; ++s)
            asm volatile("mbarrier.init.shared::cta.b64 [%0], 1;"
                         :: "r"(bar_base + 8u * s) : "memory");
        asm volatile("fence.proxy.async.shared::cta;" ::: "memory");
        #pragma unroll
        for (int s = 0; s < 2; ++s) {
            int r = (int)atomicAdd(&g_ticket, 1u);
            rowids_sm[s] = r;
            if (r < B) {
                const uint32_t mb = bar_base + 8u * s;
                const uint32_t bf = buf_base + s * rowbytes;
                const char* src = (const char*)(enc + (size_t)r * (size_t)F);
                asm volatile("mbarrier.arrive.expect_tx.shared::cta.b64 _, [%0], %1;"
                             :: "r"(mb), "r"(rowbytes) : "memory");
                #pragma unroll
                for (int q = 0; q < TMA_SPLIT; ++q) {
                    asm volatile("cp.async.bulk.shared::cta.global.mbarrier::complete_tx::bytes "
                                 "[%0], [%1], %2, [%3];"
                                 :: "r"(bf + q * qbytes), "l"(src + q * qbytes),
                                    "r"(qbytes), "r"(mb) : "memory");
                }
            }
        }
    }

    // ---- preload prefs as packed 2x16-bit byte offsets + weights (overlaps
    // the first rows' TMA fetch issued above) ----
    const int n4 = N >> 2;
    uint32_t plo[MAXCHUNK], phi[MAXCHUNK];   // (x | y<<16), (z | w<<16)
    float4 wv[MAXCHUNK];
    {
        const int4*   pref4 = (const int4*)pref;
        const float4* w4    = (const float4*)w;
        #pragma unroll
        for (int k = 0; k < MAXCHUNK; ++k) {
            int i4 = tid + k * THREADS;
            if (i4 < n4) {
                int4 p = pref4[i4];
                uint32_t ox, oy, oz, ow;
                if (fmask) {
                    ox = (uint32_t)(p.x & fmask) << 2;
                    oy = (uint32_t)(p.y & fmask) << 2;
                    oz = (uint32_t)(p.z & fmask) << 2;
                    ow = (uint32_t)(p.w & fmask) << 2;
                } else {
                    ox = ((unsigned)p.x % (unsigned)F) << 2;
                    oy = ((unsigned)p.y % (unsigned)F) << 2;
                    oz = ((unsigned)p.z % (unsigned)F) << 2;
                    ow = ((unsigned)p.w % (unsigned)F) << 2;
                }
                plo[k] = ox | (oy << 16);
                phi[k] = oz | (ow << 16);
                wv[k]  = w4[i4];
            } else {
                plo[k] = phi[k] = 0;
                wv[k] = make_float4(0.f, 0.f, 0.f, 0.f);
            }
        }
    }

    __syncthreads();   // publishes mbarrier init + rowids_sm to all threads

    int cur = 0, nxt2 = 2;   // nxt2 = (cur + 2) % STAGES
    int par = 0;

    for (;;) {
        const int r = rowids_sm[cur];   // claimed 2 iterations ago (or prologue)
        if (r >= B) break;

        // ---- claim + issue refill TMA at TOP of iteration (buffer nxt2 free
        // since before the PREVIOUS iteration's __syncthreads) ----
        if (tid == 0) {
            int r2 = (int)atomicAdd(&g_ticket, 1u);
            rowids_sm[nxt2] = r2;
            if (r2 < B) {
                const uint32_t mb = bar_base + 8u * nxt2;
                const uint32_t bf = buf_base + nxt2 * rowbytes;
                const char* src = (const char*)(enc + (size_t)r2 * (size_t)F);
                asm volatile("mbarrier.arrive.expect_tx.shared::cta.b64 _, [%0], %1;"
                             :: "r"(mb), "r"(rowbytes) : "memory");
                #pragma unroll
                for (int q = 0; q < TMA_SPLIT; ++q) {
                    asm volatile("cp.async.bulk.shared::cta.global.mbarrier::complete_tx::bytes "
                                 "[%0], [%1], %2, [%3];"
                                 :: "r"(bf + q * qbytes), "l"(src + q * qbytes),
                                    "r"(qbytes), "r"(mb) : "memory");
                }
            }
        }

        // ---- wait for current buffer ----
        {
            const uint32_t mb = bar_base + 8u * cur;
            uint32_t done;
            asm volatile("{ .reg .pred p; "
                         "mbarrier.try_wait.parity.acquire.cta.shared::cta.b64 p, [%1], %2; "
                         "selp.b32 %0, 1, 0, p; }"
                         : "=r"(done) : "r"(mb), "r"((uint32_t)par) : "memory");
            if (!done) {
                asm volatile("{ .reg .pred P1; "
                             "WL%=: mbarrier.try_wait.parity.acquire.cta.shared::cta.b64 P1, [%0], %1, 0x989680; "
                             "@P1 bra.uni WD%=; bra.uni WL%=; WD%=: }"
                             :: "r"(mb), "r"((uint32_t)par) : "memory");
            }
        }

        const char* srow = (const char*)smem_dyn + (size_t)cur * rowbytes;

        // ---- gather into registers + local sum ----
        float lsum = 0.0f;
        float4 vals[MAXCHUNK];
        #pragma unroll
        for (int k = 0; k < MAXCHUNK; ++k) {
            float4 v;
            v.x = *(const float*)(srow + (plo[k] & 0xFFFFu)) * wv[k].x;
            v.y = *(const float*)(srow + (plo[k] >> 16))     * wv[k].y;
            v.z = *(const float*)(srow + (phi[k] & 0xFFFFu)) * wv[k].z;
            v.w = *(const float*)(srow + (phi[k] >> 16))     * wv[k].w;
            vals[k] = v;
            lsum += (v.x + v.y) + (v.z + v.w);
        }

        // ---- warp partial sums ----
        #pragma unroll
        for (int off = 16; off > 0; off >>= 1)
            lsum += __shfl_down_sync(0xFFFFFFFFu, lsum, off);
        if ((tid & 31) == 0) warpsums[tid >> 5] = lsum;
        __syncthreads();   // sums visible AND all reads of srow done -> release point

        // ---- butterfly final reduce: 1 LDS + 5 SHFL, all lanes get total ----
        float tot = warpsums[tid & 31];   // THREADS/32 == 32 entries
        #pragma unroll
        for (int off = 16; off > 0; off >>= 1)
            tot += __shfl_xor_sync(0xFFFFFFFFu, tot, off);
        const float sub = (0.1f / (float)N) * tot;

        // ---- epilogue: subtract + relu, streaming float4 stores ----
        float4* out4 = (float4*)(out + (size_t)r * (size_t)N);
        #pragma unroll
        for (int k = 0; k < MAXCHUNK; ++k) {
            int i4 = tid + k * THREADS;
            float4 v = vals[k];
            float4 o;
            o.x = fmaxf(v.x - sub, 0.0f);
            o.y = fmaxf(v.y - sub, 0.0f);
            o.z = fmaxf(v.z - sub, 0.0f);
            o.w = fmaxf(v.w - sub, 0.0f);
            __stcs(out4 + i4, o);
        }

        // advance ring
        cur  = (cur == STAGES - 1) ? 0 : cur + 1;
        nxt2 = (nxt2 == STAGES - 1) ? 0 : nxt2 + 1;
        if (cur == 0) par ^= 1;
    }

    // ---- self-reset for the next (graph-replayed) launch ----
    if (tid == 0) {
        __threadfence();
        unsigned d = atomicAdd(&g_done, 1u);
        if (d == gridDim.x - 1u) {
            g_ticket = 0u;
            g_done   = 0u;
            __threadfence();
        }
    }
}

extern "C" void kernel_launch(void* const* d_in, const int* in_sizes, int n_in,
                              void* d_out, int out_size)
{
    const float* enc  = (const float*)d_in[0];
    const float* w    = (const float*)d_in[1];
    const int*   pref = (const int*)d_in[2];
    float*       out  = (float*)d_out;

    const int N = in_sizes[1];
    const int B = out_size / N;
    const int F = (int)((long long)in_sizes[0] / (long long)B);
    const int fmask = ((F & (F - 1)) == 0) ? (F - 1) : 0;

    int dev = 0;
    cudaGetDevice(&dev);
    int sms = 148;
    cudaDeviceGetAttribute(&sms, cudaDevAttrMultiProcessorCount, dev);
    int grid = (B < sms) ? B : sms;

    const int smem = STAGES * F * (int)sizeof(float);
    cudaFuncSetAttribute(sensory_persistent13,
                         cudaFuncAttributeMaxDynamicSharedMemorySize, smem);

    sensory_persistent13<<<grid, THREADS, smem>>>(enc, w, pref, out, B, N, F, fmask);
}